// round 1
// baseline (speedup 1.0000x reference)
#include <cuda_runtime.h>
#include <cuda_bf16.h>
#include <math.h>

// Problem constants
#define BB 8
#define CC 1024
#define LL 32
#define NN 8192          // B*C
#define DD 128
#define HH 4
#define HO 512           // H*D
#define RR 3
#define AA 64
#define ENBR 262144      // N*L
#define EPS 1e-5f
#define SCALE 0.08838834764831845f   // 1/sqrt(128)

// ---------------- static device scratch (no runtime allocation) ----------------
__device__ float g_x[NN * DD];
__device__ float g_q[NN * HO];
__device__ float g_k[NN * HO];
__device__ float g_v[NN * HO];
__device__ float g_t[NN * HO];      // holds skip, then skip+agg
__device__ float g_M[2 * HO];       // per-round (We_emb @ Wedge)
__device__ int   g_indptr[NN + 1];
__device__ int   g_cnt[NN];
__device__ int   g_cursor[NN];
__device__ int   g_esrc[ENBR];
__device__ float2 g_erel[ENBR];
__device__ int   g_fmt[1];          // 1 if ids are int64, 0 if int32

// ---------------- helpers ----------------
__global__ void detect_fmt_kernel(const int* __restrict__ ids) {
    // int64 little-endian: odd words are high words == 0 (values < 1024).
    // int32: odd words are random ids in [0,1024), practically never all zero.
    int nz = 0;
    for (int i = threadIdx.x; i < 64; i += 32)
        nz |= (ids[2 * i + 1] != 0);
    nz = __any_sync(0xffffffffu, nz);
    if (threadIdx.x == 0) g_fmt[0] = nz ? 0 : 1;
}

__global__ void copy_x_kernel(const float* __restrict__ src) {
    int i = blockIdx.x * blockDim.x + threadIdx.x;
    if (i < NN * DD) g_x[i] = src[i];
}

__global__ void zero_cnt_kernel() {
    int i = blockIdx.x * blockDim.x + threadIdx.x;
    if (i < NN) g_cnt[i] = 0;
}

__device__ __forceinline__ int load_id(const int* __restrict__ ids, int idx, int fmt64) {
    return fmt64 ? ids[2 * idx] : ids[idx];
}

__global__ void count_kernel(const int* __restrict__ ids) {
    int idx = blockIdx.x * blockDim.x + threadIdx.x;
    if (idx >= ENBR) return;
    int fmt = g_fmt[0];
    int id = load_id(ids, idx, fmt);
    int n = idx >> 5;                 // agent (L=32)
    int dst = (n & ~(CC - 1)) | id;   // batch*C + id
    atomicAdd(&g_cnt[dst], 1);
}

__global__ void scan_kernel() {
    __shared__ int partials[1024];
    int t = threadIdx.x;
    int local[8];
    int s = 0;
#pragma unroll
    for (int i = 0; i < 8; i++) { local[i] = g_cnt[t * 8 + i]; s += local[i]; }
    partials[t] = s;
    __syncthreads();
    // Hillis-Steele inclusive scan
    for (int off = 1; off < 1024; off <<= 1) {
        int val = (t >= off) ? partials[t - off] : 0;
        __syncthreads();
        partials[t] += val;
        __syncthreads();
    }
    int run = (t == 0) ? 0 : partials[t - 1];
#pragma unroll
    for (int i = 0; i < 8; i++) {
        g_indptr[t * 8 + i] = run;
        g_cursor[t * 8 + i] = run;
        run += local[i];
    }
    if (t == 1023) g_indptr[NN] = run;
}

__global__ void scatter_kernel(const int* __restrict__ ids, const float* __restrict__ rc) {
    int idx = blockIdx.x * blockDim.x + threadIdx.x;
    if (idx >= ENBR) return;
    int fmt = g_fmt[0];
    int id = load_id(ids, idx, fmt);
    int n = idx >> 5;
    int l = idx & 31;
    int dst = (n & ~(CC - 1)) | id;
    int pos = atomicAdd(&g_cursor[dst], 1);
    g_esrc[pos] = n;
    g_erel[pos] = make_float2(rc[n * (2 * LL) + 2 * l], rc[n * (2 * LL) + 2 * l + 1]);
}

// M[2,HO] = We_emb[r] (2xD) @ Wedge[r] (DxHO)
__global__ void gemmM_kernel(const float* __restrict__ We, const float* __restrict__ Wedge) {
    int o = threadIdx.x;   // 512 threads
    float s0 = 0.f, s1 = 0.f;
    for (int d = 0; d < DD; d++) {
        float w = Wedge[d * HO + o];
        s0 += We[d] * w;
        s1 += We[DD + d] * w;
    }
    g_M[o] = s0;
    g_M[HO + o] = s1;
}

// ---------------- SGEMM: C = A[M,K] @ B[K,N], row-major, M%64==0, N%64==0, K%16==0 ----------------
#define BM 64
#define BN 64
#define BKK 16
__global__ __launch_bounds__(256) void sgemm_kernel(
    const float* __restrict__ A,
    const float* __restrict__ B0, const float* __restrict__ B1,
    const float* __restrict__ B2, const float* __restrict__ B3,
    float* __restrict__ C0, float* __restrict__ C1,
    float* __restrict__ C2, float* __restrict__ C3,
    int Mdim, int Ndim, int Kdim)
{
    const float* Bp;
    float* Cp;
    switch (blockIdx.z) {
        case 0: Bp = B0; Cp = C0; break;
        case 1: Bp = B1; Cp = C1; break;
        case 2: Bp = B2; Cp = C2; break;
        default: Bp = B3; Cp = C3; break;
    }
    __shared__ float As[BKK][BM + 4];  // 68-float rows, 16B aligned
    __shared__ float Bs[BKK][BN];
    int tid = threadIdx.x;
    int bm = blockIdx.y * BM, bn = blockIdx.x * BN;
    int tx = tid & 15, ty = tid >> 4;
    int arow = tid >> 2, ac4 = tid & 3;
    int brow = tid >> 4, bc4 = tid & 15;

    float acc[4][4];
#pragma unroll
    for (int i = 0; i < 4; i++)
#pragma unroll
        for (int j = 0; j < 4; j++) acc[i][j] = 0.f;

    for (int kt = 0; kt < Kdim; kt += BKK) {
        float4 av = *(const float4*)(A + (size_t)(bm + arow) * Kdim + kt + ac4 * 4);
        float4 bv = *(const float4*)(Bp + (size_t)(kt + brow) * Ndim + bn + bc4 * 4);
        As[ac4 * 4 + 0][arow] = av.x;
        As[ac4 * 4 + 1][arow] = av.y;
        As[ac4 * 4 + 2][arow] = av.z;
        As[ac4 * 4 + 3][arow] = av.w;
        *(float4*)(&Bs[brow][bc4 * 4]) = bv;
        __syncthreads();
#pragma unroll
        for (int kk = 0; kk < BKK; kk++) {
            float4 a = *(const float4*)(&As[kk][ty * 4]);
            float4 b = *(const float4*)(&Bs[kk][tx * 4]);
            float ar[4] = {a.x, a.y, a.z, a.w};
            float br[4] = {b.x, b.y, b.z, b.w};
#pragma unroll
            for (int i = 0; i < 4; i++)
#pragma unroll
                for (int j = 0; j < 4; j++) acc[i][j] += ar[i] * br[j];
        }
        __syncthreads();
    }
#pragma unroll
    for (int i = 0; i < 4; i++) {
        float4 o = make_float4(acc[i][0], acc[i][1], acc[i][2], acc[i][3]);
        *(float4*)(Cp + (size_t)(bm + ty * 4 + i) * Ndim + bn + tx * 4) = o;
    }
}

// ---------------- attention: block per dst node, warp per head, online softmax ----------------
__global__ __launch_bounds__(128) void attn_kernel() {
    int j = blockIdx.x;
    int warp = threadIdx.x >> 5;
    int lane = threadIdx.x & 31;
    __shared__ float sM[2 * HO];
    for (int i = threadIdx.x; i < 2 * HO; i += 128) sM[i] = g_M[i];
    __syncthreads();

    const int base = warp * DD + lane;   // hd index, lane stride 32
    float qr[4];
#pragma unroll
    for (int u = 0; u < 4; u++) qr[u] = g_q[(size_t)j * HO + base + 32 * u];

    // self edge (edge_attr = 0 -> e = 0)
    float m, den, acc[4];
    {
        float part = 0.f;
#pragma unroll
        for (int u = 0; u < 4; u++) {
            float kv = g_k[(size_t)j * HO + base + 32 * u];
            part += qr[u] * kv;
            acc[u] = g_v[(size_t)j * HO + base + 32 * u];
        }
#pragma unroll
        for (int o = 16; o; o >>= 1) part += __shfl_xor_sync(0xffffffffu, part, o);
        m = part * SCALE;
        den = 1.f;
    }

    int e0 = g_indptr[j], e1 = g_indptr[j + 1];
    for (int ei = e0; ei < e1; ++ei) {
        int s = g_esrc[ei];
        float2 rr = g_erel[ei];
        float e[4];
        float part = 0.f;
#pragma unroll
        for (int u = 0; u < 4; u++) {
            int hd = base + 32 * u;
            e[u] = rr.x * sM[hd] + rr.y * sM[HO + hd];
            part += qr[u] * (g_k[(size_t)s * HO + hd] + e[u]);
        }
#pragma unroll
        for (int o = 16; o; o >>= 1) part += __shfl_xor_sync(0xffffffffu, part, o);
        float alpha = part * SCALE;
        float mn = fmaxf(m, alpha);
        float fold = __expf(m - mn);
        float w = __expf(alpha - mn);
        den = den * fold + w;
#pragma unroll
        for (int u = 0; u < 4; u++) {
            acc[u] = acc[u] * fold + w * (g_v[(size_t)s * HO + base + 32 * u] + e[u]);
        }
        m = mn;
    }

    float inv = 1.f / den;
#pragma unroll
    for (int u = 0; u < 4; u++) {
        size_t idx = (size_t)j * HO + base + 32 * u;
        g_t[idx] = g_t[idx] + acc[u] * inv;   // t held skip; now skip+agg
    }
}

// x = rmsnorm(o + x, ln_w)
__global__ __launch_bounds__(128) void rmsres_kernel(const float* __restrict__ o,
                                                     const float* __restrict__ lnw) {
    int j = blockIdx.x, d = threadIdx.x;
    float val = o[(size_t)j * DD + d] + g_x[(size_t)j * DD + d];
    float ss = val * val;
#pragma unroll
    for (int off = 16; off; off >>= 1) ss += __shfl_xor_sync(0xffffffffu, ss, off);
    __shared__ float w4[4];
    if ((threadIdx.x & 31) == 0) w4[threadIdx.x >> 5] = ss;
    __syncthreads();
    float tot = w4[0] + w4[1] + w4[2] + w4[3];
    float r = rsqrtf(tot / (float)DD + EPS);
    g_x[(size_t)j * DD + d] = val * r * lnw[d];
}

// out = rmsnorm(y, ln_f)
__global__ __launch_bounds__(64) void rmsfinal_kernel(const float* __restrict__ y,
                                                      const float* __restrict__ lnf,
                                                      float* __restrict__ out) {
    int j = blockIdx.x, d = threadIdx.x;
    float val = y[(size_t)j * AA + d];
    float ss = val * val;
#pragma unroll
    for (int off = 16; off; off >>= 1) ss += __shfl_xor_sync(0xffffffffu, ss, off);
    __shared__ float w2[2];
    if ((threadIdx.x & 31) == 0) w2[threadIdx.x >> 5] = ss;
    __syncthreads();
    float tot = w2[0] + w2[1];
    float r = rsqrtf(tot / (float)AA + EPS);
    out[(size_t)j * AA + d] = val * r * lnf[d];
}

// ---------------- launch ----------------
extern "C" void kernel_launch(void* const* d_in, const int* in_sizes, int n_in,
                              void* d_out, int out_size) {
    const float* node_features = (const float*)d_in[0];
    const int*   ids           = (const int*)d_in[1];
    const float* rel           = (const float*)d_in[2];
    const float* We_emb        = (const float*)d_in[3];
    const float* Wq            = (const float*)d_in[4];
    const float* Wk            = (const float*)d_in[5];
    const float* Wv            = (const float*)d_in[6];
    const float* Wedge         = (const float*)d_in[7];
    const float* Wskip         = (const float*)d_in[8];
    const float* Wout          = (const float*)d_in[9];
    const float* lnw           = (const float*)d_in[10];
    const float* Wact          = (const float*)d_in[11];
    const float* lnf           = (const float*)d_in[12];
    float* out = (float*)d_out;

    float *xp, *qp, *kp, *vp, *tp;
    cudaGetSymbolAddress((void**)&xp, g_x);
    cudaGetSymbolAddress((void**)&qp, g_q);
    cudaGetSymbolAddress((void**)&kp, g_k);
    cudaGetSymbolAddress((void**)&vp, g_v);
    cudaGetSymbolAddress((void**)&tp, g_t);

    detect_fmt_kernel<<<1, 32>>>(ids);
    copy_x_kernel<<<(NN * DD + 255) / 256, 256>>>(node_features);
    zero_cnt_kernel<<<(NN + 255) / 256, 256>>>();
    count_kernel<<<(ENBR + 255) / 256, 256>>>(ids);
    scan_kernel<<<1, 1024>>>();
    scatter_kernel<<<(ENBR + 255) / 256, 256>>>(ids, rel);

    for (int r = 0; r < RR; r++) {
        gemmM_kernel<<<1, HO>>>(We_emb + (size_t)r * 2 * DD, Wedge + (size_t)r * DD * HO);

        // q, k, v, skip
        const float* wq = Wq + (size_t)r * DD * HO;
        const float* wk = Wk + (size_t)r * DD * HO;
        const float* wv = Wv + (size_t)r * DD * HO;
        const float* ws = Wskip + (size_t)r * DD * HO;
        dim3 g4(HO / BN, NN / BM, 4);
        sgemm_kernel<<<g4, 256>>>(xp, wq, wk, wv, ws, qp, kp, vp, tp, NN, HO, DD);

        attn_kernel<<<NN, 128>>>();

        // out-proj: g_t @ Wout[r] -> g_q (scratch)
        const float* wo = Wout + (size_t)r * HO * DD;
        dim3 go(DD / BN, NN / BM, 1);
        sgemm_kernel<<<go, 256>>>(tp, wo, wo, wo, wo, qp, qp, qp, qp, NN, DD, HO);

        rmsres_kernel<<<NN, DD>>>(qp, lnw + (size_t)r * DD);
    }

    // final: g_x @ Wact -> g_k (scratch), then rmsnorm to out
    dim3 gf(AA / BN, NN / BM, 1);
    sgemm_kernel<<<gf, 256>>>(xp, Wact, Wact, Wact, Wact, kp, kp, kp, kp, NN, AA, DD);
    rmsfinal_kernel<<<NN, AA>>>(kp, lnf, out);
}

// round 3
// speedup vs baseline: 1.3036x; 1.3036x over previous
#include <cuda_runtime.h>
#include <cuda_bf16.h>
#include <math.h>

// Problem constants
#define BB 8
#define CC 1024
#define LL 32
#define NN 8192          // B*C
#define DD 128
#define HH 4
#define HO 512           // H*D
#define RR 3
#define AA 64
#define ENBR 262144      // N*L
#define EPS 1e-5f
#define SCALE 0.08838834764831845f   // 1/sqrt(128)

// ---------------- static device scratch ----------------
__device__ float g_x[NN * DD];
__device__ float g_q[NN * HO];
__device__ float g_k[NN * HO];
__device__ float g_v[NN * HO];
__device__ float g_t[NN * HO];      // holds skip, then skip+agg
__device__ float g_M[2 * HO];       // per-round (We_emb @ Wedge)
__device__ int   g_indptr[NN + 1];
__device__ int   g_cnt[NN];
__device__ int   g_cursor[NN];
__device__ int   g_esrc[ENBR];
__device__ float2 g_erel[ENBR];
__device__ int   g_fmt[1];          // 1 if ids are int64, 0 if int32

// ---------------- helpers ----------------
__global__ void detect_fmt_kernel(const int* __restrict__ ids) {
    int nz = 0;
    for (int i = threadIdx.x; i < 64; i += 32)
        nz |= (ids[2 * i + 1] != 0);
    nz = __any_sync(0xffffffffu, nz);
    if (threadIdx.x == 0) g_fmt[0] = nz ? 0 : 1;
}

__global__ void copy_x_kernel(const float* __restrict__ src) {
    int i = blockIdx.x * blockDim.x + threadIdx.x;
    if (i < NN * DD) g_x[i] = src[i];
}

__global__ void zero_cnt_kernel() {
    int i = blockIdx.x * blockDim.x + threadIdx.x;
    if (i < NN) g_cnt[i] = 0;
}

__device__ __forceinline__ int load_id(const int* __restrict__ ids, int idx, int fmt64) {
    return fmt64 ? ids[2 * idx] : ids[idx];
}

__global__ void count_kernel(const int* __restrict__ ids) {
    int idx = blockIdx.x * blockDim.x + threadIdx.x;
    if (idx >= ENBR) return;
    int fmt = g_fmt[0];
    int id = load_id(ids, idx, fmt);
    int n = idx >> 5;
    int dst = (n & ~(CC - 1)) | id;
    atomicAdd(&g_cnt[dst], 1);
}

__global__ void scan_kernel() {
    __shared__ int partials[1024];
    int t = threadIdx.x;
    int local[8];
    int s = 0;
#pragma unroll
    for (int i = 0; i < 8; i++) { local[i] = g_cnt[t * 8 + i]; s += local[i]; }
    partials[t] = s;
    __syncthreads();
    for (int off = 1; off < 1024; off <<= 1) {
        int val = (t >= off) ? partials[t - off] : 0;
        __syncthreads();
        partials[t] += val;
        __syncthreads();
    }
    int run = (t == 0) ? 0 : partials[t - 1];
#pragma unroll
    for (int i = 0; i < 8; i++) {
        g_indptr[t * 8 + i] = run;
        g_cursor[t * 8 + i] = run;
        run += local[i];
    }
    if (t == 1023) g_indptr[NN] = run;
}

__global__ void scatter_kernel(const int* __restrict__ ids, const float* __restrict__ rc) {
    int idx = blockIdx.x * blockDim.x + threadIdx.x;
    if (idx >= ENBR) return;
    int fmt = g_fmt[0];
    int id = load_id(ids, idx, fmt);
    int n = idx >> 5;
    int l = idx & 31;
    int dst = (n & ~(CC - 1)) | id;
    int pos = atomicAdd(&g_cursor[dst], 1);
    g_esrc[pos] = n;
    g_erel[pos] = make_float2(rc[n * (2 * LL) + 2 * l], rc[n * (2 * LL) + 2 * l + 1]);
}

// M[2,HO] = We_emb[r] (2xD) @ Wedge[r] (DxHO)
__global__ void gemmM_kernel(const float* __restrict__ We, const float* __restrict__ Wedge) {
    int o = threadIdx.x;
    float s0 = 0.f, s1 = 0.f;
    for (int d = 0; d < DD; d++) {
        float w = Wedge[d * HO + o];
        s0 += We[d] * w;
        s1 += We[DD + d] * w;
    }
    g_M[o] = s0;
    g_M[HO + o] = s1;
}

// ---------------- tf32 tensor-core GEMM ----------------
// C[M=grid.y*128, N] = A[M,K] @ B[K,N], all row-major fp32, tf32 MMA + fp32 accum.
// CTA tile 128x64, K-chunk 32, 256 threads = 8 warps (4 along M x 2 along N),
// warp tile 32x32 (2 m16 x 4 n8 mma tiles). Register prefetch of next chunk.

__device__ __forceinline__ unsigned f2tf32(float x) {
    unsigned r;
    asm("cvt.rna.tf32.f32 %0, %1;" : "=r"(r) : "f"(x));
    return r;
}

__device__ __forceinline__ void mma_tf32(float* c, unsigned a0, unsigned a1, unsigned a2,
                                         unsigned a3, unsigned b0, unsigned b1) {
    asm volatile(
        "mma.sync.aligned.m16n8k8.row.col.f32.tf32.tf32.f32 "
        "{%0,%1,%2,%3}, {%4,%5,%6,%7}, {%8,%9}, {%0,%1,%2,%3};"
        : "+f"(c[0]), "+f"(c[1]), "+f"(c[2]), "+f"(c[3])
        : "r"(a0), "r"(a1), "r"(a2), "r"(a3), "r"(b0), "r"(b1));
}

#define ASTRIDE 136   // 128 + 8 pad (conflict-free fragment reads)
#define BSTRIDE 72    // 64 + 8 pad

__global__ __launch_bounds__(256) void tf32gemm_kernel(
    const float* __restrict__ A,
    const float* __restrict__ B0, const float* __restrict__ B1,
    const float* __restrict__ B2, const float* __restrict__ B3,
    float* __restrict__ C0, float* __restrict__ C1,
    float* __restrict__ C2, float* __restrict__ C3,
    int Ndim, int Kdim)
{
    const float* Bp;
    float* Cp;
    switch (blockIdx.z) {
        case 0: Bp = B0; Cp = C0; break;
        case 1: Bp = B1; Cp = C1; break;
        case 2: Bp = B2; Cp = C2; break;
        default: Bp = B3; Cp = C3; break;
    }
    __shared__ unsigned As[32][ASTRIDE];  // [k][m]
    __shared__ unsigned Bs[32][BSTRIDE];  // [k][n]

    const int tid = threadIdx.x;
    const int bm = blockIdx.y * 128, bn = blockIdx.x * 64;
    const int lane = tid & 31;
    const int w = tid >> 5;
    const int wm = w & 3;        // 0..3 along M
    const int wn = w >> 2;       // 0..1 along N
    const int lq = lane >> 2;    // 0..7
    const int lr = lane & 3;     // 0..3

    float4 areg[4];
    float4 breg[2];

    const int nch = Kdim >> 5;

#define LOADA(c)                                                                 \
    _Pragma("unroll") for (int f = 0; f < 4; f++) {                              \
        int id = tid + 256 * f;                                                  \
        areg[f] = *(const float4*)(A + (size_t)(bm + (id >> 3)) * Kdim +         \
                                   (c) * 32 + (id & 7) * 4);                     \
    }
#define LOADB(c)                                                                 \
    _Pragma("unroll") for (int f = 0; f < 2; f++) {                              \
        int id = tid + 256 * f;                                                  \
        breg[f] = *(const float4*)(Bp + (size_t)((c) * 32 + (id >> 4)) * Ndim +  \
                                   bn + (id & 15) * 4);                          \
    }

    float acc[2][4][4];
#pragma unroll
    for (int i = 0; i < 2; i++)
#pragma unroll
        for (int j = 0; j < 4; j++)
#pragma unroll
            for (int u = 0; u < 4; u++) acc[i][j][u] = 0.f;

    LOADA(0);
    LOADB(0);

    for (int c = 0;;) {
        __syncthreads();
#pragma unroll
        for (int f = 0; f < 4; f++) {
            int id = tid + 256 * f;
            int row = id >> 3, kq = id & 7;
            As[kq * 4 + 0][row] = f2tf32(areg[f].x);
            As[kq * 4 + 1][row] = f2tf32(areg[f].y);
            As[kq * 4 + 2][row] = f2tf32(areg[f].z);
            As[kq * 4 + 3][row] = f2tf32(areg[f].w);
        }
#pragma unroll
        for (int f = 0; f < 2; f++) {
            int id = tid + 256 * f;
            int row = id >> 4, nq = id & 15;
            Bs[row][nq * 4 + 0] = f2tf32(breg[f].x);
            Bs[row][nq * 4 + 1] = f2tf32(breg[f].y);
            Bs[row][nq * 4 + 2] = f2tf32(breg[f].z);
            Bs[row][nq * 4 + 3] = f2tf32(breg[f].w);
        }
        __syncthreads();

        bool last = (c == nch - 1);
        if (!last) { LOADA(c + 1); LOADB(c + 1); }

#pragma unroll
        for (int kk = 0; kk < 4; kk++) {
            int k0 = kk * 8;
            unsigned a[2][4];
#pragma unroll
            for (int i = 0; i < 2; i++) {
                int mr = wm * 32 + i * 16 + lq;
                a[i][0] = As[k0 + lr][mr];
                a[i][1] = As[k0 + lr][mr + 8];
                a[i][2] = As[k0 + lr + 4][mr];
                a[i][3] = As[k0 + lr + 4][mr + 8];
            }
            unsigned b[4][2];
#pragma unroll
            for (int j = 0; j < 4; j++) {
                int nb = wn * 32 + j * 8 + lq;
                b[j][0] = Bs[k0 + lr][nb];
                b[j][1] = Bs[k0 + lr + 4][nb];
            }
#pragma unroll
            for (int i = 0; i < 2; i++)
#pragma unroll
                for (int j = 0; j < 4; j++)
                    mma_tf32(acc[i][j], a[i][0], a[i][1], a[i][2], a[i][3],
                             b[j][0], b[j][1]);
        }
        if (last) break;
        c++;
    }

    // epilogue
#pragma unroll
    for (int i = 0; i < 2; i++) {
#pragma unroll
        for (int j = 0; j < 4; j++) {
            int row = bm + wm * 32 + i * 16 + lq;
            int col = bn + wn * 32 + j * 8 + lr * 2;
            *(float2*)(Cp + (size_t)row * Ndim + col) =
                make_float2(acc[i][j][0], acc[i][j][1]);
            *(float2*)(Cp + (size_t)(row + 8) * Ndim + col) =
                make_float2(acc[i][j][2], acc[i][j][3]);
        }
    }
}

// ---------------- attention: block per dst node, warp per head, online softmax ----------------
__global__ __launch_bounds__(128) void attn_kernel() {
    int j = blockIdx.x;
    int warp = threadIdx.x >> 5;
    int lane = threadIdx.x & 31;
    __shared__ float sM[2 * HO];
    for (int i = threadIdx.x; i < 2 * HO; i += 128) sM[i] = g_M[i];
    __syncthreads();

    const int base = warp * DD + lane;
    float qr[4];
#pragma unroll
    for (int u = 0; u < 4; u++) qr[u] = g_q[(size_t)j * HO + base + 32 * u];

    float m, den, acc[4];
    {
        float part = 0.f;
#pragma unroll
        for (int u = 0; u < 4; u++) {
            float kv = g_k[(size_t)j * HO + base + 32 * u];
            part += qr[u] * kv;
            acc[u] = g_v[(size_t)j * HO + base + 32 * u];
        }
#pragma unroll
        for (int o = 16; o; o >>= 1) part += __shfl_xor_sync(0xffffffffu, part, o);
        m = part * SCALE;
        den = 1.f;
    }

    int e0 = g_indptr[j], e1 = g_indptr[j + 1];
    for (int ei = e0; ei < e1; ++ei) {
        int s = g_esrc[ei];
        float2 rr = g_erel[ei];
        float e[4];
        float part = 0.f;
#pragma unroll
        for (int u = 0; u < 4; u++) {
            int hd = base + 32 * u;
            e[u] = rr.x * sM[hd] + rr.y * sM[HO + hd];
            part += qr[u] * (g_k[(size_t)s * HO + hd] + e[u]);
        }
#pragma unroll
        for (int o = 16; o; o >>= 1) part += __shfl_xor_sync(0xffffffffu, part, o);
        float alpha = part * SCALE;
        float mn = fmaxf(m, alpha);
        float fold = __expf(m - mn);
        float wgt = __expf(alpha - mn);
        den = den * fold + wgt;
#pragma unroll
        for (int u = 0; u < 4; u++) {
            acc[u] = acc[u] * fold + wgt * (g_v[(size_t)s * HO + base + 32 * u] + e[u]);
        }
        m = mn;
    }

    float inv = 1.f / den;
#pragma unroll
    for (int u = 0; u < 4; u++) {
        size_t idx = (size_t)j * HO + base + 32 * u;
        g_t[idx] = g_t[idx] + acc[u] * inv;
    }
}

// x = rmsnorm(o + x, ln_w)
__global__ __launch_bounds__(128) void rmsres_kernel(const float* __restrict__ o,
                                                     const float* __restrict__ lnw) {
    int j = blockIdx.x, d = threadIdx.x;
    float val = o[(size_t)j * DD + d] + g_x[(size_t)j * DD + d];
    float ss = val * val;
#pragma unroll
    for (int off = 16; off; off >>= 1) ss += __shfl_xor_sync(0xffffffffu, ss, off);
    __shared__ float w4[4];
    if ((threadIdx.x & 31) == 0) w4[threadIdx.x >> 5] = ss;
    __syncthreads();
    float tot = w4[0] + w4[1] + w4[2] + w4[3];
    float r = rsqrtf(tot / (float)DD + EPS);
    g_x[(size_t)j * DD + d] = val * r * lnw[d];
}

// out = rmsnorm(y, ln_f)
__global__ __launch_bounds__(64) void rmsfinal_kernel(const float* __restrict__ y,
                                                      const float* __restrict__ lnf,
                                                      float* __restrict__ out) {
    int j = blockIdx.x, d = threadIdx.x;
    float val = y[(size_t)j * AA + d];
    float ss = val * val;
#pragma unroll
    for (int off = 16; off; off >>= 1) ss += __shfl_xor_sync(0xffffffffu, ss, off);
    __shared__ float w2[2];
    if ((threadIdx.x & 31) == 0) w2[threadIdx.x >> 5] = ss;
    __syncthreads();
    float tot = w2[0] + w2[1];
    float r = rsqrtf(tot / (float)AA + EPS);
    out[(size_t)j * AA + d] = val * r * lnf[d];
}

// ---------------- launch ----------------
extern "C" void kernel_launch(void* const* d_in, const int* in_sizes, int n_in,
                              void* d_out, int out_size) {
    const float* node_features = (const float*)d_in[0];
    const int*   ids           = (const int*)d_in[1];
    const float* rel           = (const float*)d_in[2];
    const float* We_emb        = (const float*)d_in[3];
    const float* Wq            = (const float*)d_in[4];
    const float* Wk            = (const float*)d_in[5];
    const float* Wv            = (const float*)d_in[6];
    const float* Wedge         = (const float*)d_in[7];
    const float* Wskip         = (const float*)d_in[8];
    const float* Wout          = (const float*)d_in[9];
    const float* lnw           = (const float*)d_in[10];
    const float* Wact          = (const float*)d_in[11];
    const float* lnf           = (const float*)d_in[12];
    float* out = (float*)d_out;

    float *xp, *qp, *kp, *vp, *tp;
    cudaGetSymbolAddress((void**)&xp, g_x);
    cudaGetSymbolAddress((void**)&qp, g_q);
    cudaGetSymbolAddress((void**)&kp, g_k);
    cudaGetSymbolAddress((void**)&vp, g_v);
    cudaGetSymbolAddress((void**)&tp, g_t);

    detect_fmt_kernel<<<1, 32>>>(ids);
    copy_x_kernel<<<(NN * DD + 255) / 256, 256>>>(node_features);
    zero_cnt_kernel<<<(NN + 255) / 256, 256>>>();
    count_kernel<<<(ENBR + 255) / 256, 256>>>(ids);
    scan_kernel<<<1, 1024>>>();
    scatter_kernel<<<(ENBR + 255) / 256, 256>>>(ids, rel);

    for (int r = 0; r < RR; r++) {
        gemmM_kernel<<<1, HO>>>(We_emb + (size_t)r * 2 * DD, Wedge + (size_t)r * DD * HO);

        const float* wq = Wq + (size_t)r * DD * HO;
        const float* wk = Wk + (size_t)r * DD * HO;
        const float* wv = Wv + (size_t)r * DD * HO;
        const float* ws = Wskip + (size_t)r * DD * HO;
        dim3 g4(HO / 64, NN / 128, 4);
        tf32gemm_kernel<<<g4, 256>>>(xp, wq, wk, wv, ws, qp, kp, vp, tp, HO, DD);

        attn_kernel<<<NN, 128>>>();

        const float* wo = Wout + (size_t)r * HO * DD;
        dim3 go(DD / 64, NN / 128, 1);
        tf32gemm_kernel<<<go, 256>>>(tp, wo, wo, wo, wo, qp, qp, qp, qp, DD, HO);

        rmsres_kernel<<<NN, DD>>>(qp, lnw + (size_t)r * DD);
    }

    dim3 gf(AA / 64, NN / 128, 1);
    tf32gemm_kernel<<<gf, 256>>>(xp, Wact, Wact, Wact, Wact, kp, kp, kp, kp, AA, DD);
    rmsfinal_kernel<<<NN, AA>>>(kp, lnf, out);
}